// round 5
// baseline (speedup 1.0000x reference)
#include <cuda_runtime.h>
#include <cuda_bf16.h>

#define DIM   128
#define NNB   64
#define WARPS 2        // rows per block (fine-grained load balance)

// One warp per batch row. Lane l owns dims [4l, 4l+3] (float4).
// Software-pipelined gather: two 4-row float4 buffers rotate so that loads
// for the next group are in flight while the current group's FMAs retire.
__global__ void __launch_bounds__(32 * WARPS, 16)
net_gather_kernel(const int* __restrict__ data_r,
                  const int* __restrict__ data_e,
                  const int* __restrict__ rel,
                  const int* __restrict__ pos_id,
                  const int* __restrict__ neg_id,
                  const float* __restrict__ ent_emb,
                  const float* __restrict__ edge_w,
                  const float* __restrict__ rel_emb,
                  float* __restrict__ out,
                  int B)
{
    const int w    = threadIdx.x >> 5;
    const int lane = threadIdx.x & 31;
    const int b    = blockIdx.x * WARPS + w;

    __shared__ int   s_e[WARPS][NNB];   // entity row index * 32 (float4 stride)
    __shared__ float s_w[WARPS][NNB];   // softmax weights

    const int base = b * NNB;
    s_e[w][lane]      = data_e[base + lane]      * (DIM / 4);
    s_e[w][lane + 32] = data_e[base + lane + 32] * (DIM / 4);
    float l0 = __ldg(&edge_w[data_r[base + lane]]);
    float l1 = __ldg(&edge_w[data_r[base + lane + 32]]);

    // Warp-local softmax over 64 logits (2 per lane).
    float m = fmaxf(l0, l1);
    #pragma unroll
    for (int off = 16; off > 0; off >>= 1)
        m = fmaxf(m, __shfl_xor_sync(0xffffffffu, m, off));
    float x0 = __expf(l0 - m);
    float x1 = __expf(l1 - m);
    float s = x0 + x1;
    #pragma unroll
    for (int off = 16; off > 0; off >>= 1)
        s += __shfl_xor_sync(0xffffffffu, s, off);
    float inv = __frcp_rn(s);
    s_w[w][lane]      = x0 * inv;
    s_w[w][lane + 32] = x1 * inv;
    __syncwarp();

    const float4* __restrict__ emb4 = (const float4*)ent_emb;   // row stride 32

    // Independent per-row lookups issued early (overlap with gather loop).
    float4 rv = __ldg(&((const float4*)rel_emb)[rel[b] * (DIM / 4) + lane]);
    float4 pv = __ldg(&emb4[pos_id[b] * (DIM / 4) + lane]);
    float4 nv = __ldg(&emb4[neg_id[b] * (DIM / 4) + lane]);

    float4 A = make_float4(0.f, 0.f, 0.f, 0.f);
    float4 C = make_float4(0.f, 0.f, 0.f, 0.f);

    // Pipelined gather: v0 holds rows [j, j+4), v1 rows [j+4, j+8).
    float4 v0[4], v1[4];
    #pragma unroll
    for (int k = 0; k < 4; k++)
        v0[k] = __ldg(&emb4[s_e[w][k] + lane]);

    #pragma unroll
    for (int j = 0; j < NNB; j += 8) {
        // issue loads for rows [j+4, j+8) before consuming v0
        #pragma unroll
        for (int k = 0; k < 4; k++)
            v1[k] = __ldg(&emb4[s_e[w][j + 4 + k] + lane]);

        #pragma unroll
        for (int k = 0; k < 4; k += 2) {
            float wa = s_w[w][j + k], wb = s_w[w][j + k + 1];
            A.x = fmaf(wa, v0[k].x, A.x);  C.x = fmaf(wb, v0[k + 1].x, C.x);
            A.y = fmaf(wa, v0[k].y, A.y);  C.y = fmaf(wb, v0[k + 1].y, C.y);
            A.z = fmaf(wa, v0[k].z, A.z);  C.z = fmaf(wb, v0[k + 1].z, C.z);
            A.w = fmaf(wa, v0[k].w, A.w);  C.w = fmaf(wb, v0[k + 1].w, C.w);
        }

        // issue loads for rows [j+8, j+12) before consuming v1 (skip on last)
        if (j + 8 < NNB) {
            #pragma unroll
            for (int k = 0; k < 4; k++)
                v0[k] = __ldg(&emb4[s_e[w][j + 8 + k] + lane]);
        }

        #pragma unroll
        for (int k = 0; k < 4; k += 2) {
            float wa = s_w[w][j + 4 + k], wb = s_w[w][j + 5 + k];
            A.x = fmaf(wa, v1[k].x, A.x);  C.x = fmaf(wb, v1[k + 1].x, C.x);
            A.y = fmaf(wa, v1[k].y, A.y);  C.y = fmaf(wb, v1[k + 1].y, C.y);
            A.z = fmaf(wa, v1[k].z, A.z);  C.z = fmaf(wb, v1[k + 1].z, C.z);
            A.w = fmaf(wa, v1[k].w, A.w);  C.w = fmaf(wb, v1[k + 1].w, C.w);
        }
    }

    float4 o;
    o.x = A.x + C.x + rv.x;
    o.y = A.y + C.y + rv.y;
    o.z = A.z + C.z + rv.z;
    o.w = A.w + C.w + rv.w;

    float4* out4 = (float4*)out;
    const int bd = b * (DIM / 4) + lane;
    const int BD = B * (DIM / 4);
    out4[bd]          = o;
    out4[BD + bd]     = pv;
    out4[2 * BD + bd] = nv;
}

extern "C" void kernel_launch(void* const* d_in, const int* in_sizes, int n_in,
                              void* d_out, int out_size)
{
    const int*   data_r  = (const int*)  d_in[0];
    const int*   data_e  = (const int*)  d_in[1];
    const int*   rel     = (const int*)  d_in[2];
    const int*   pos_id  = (const int*)  d_in[3];
    const int*   neg_id  = (const int*)  d_in[4];
    const float* ent_emb = (const float*)d_in[5];
    const float* edge_w  = (const float*)d_in[6];
    const float* rel_emb = (const float*)d_in[7];
    float* out = (float*)d_out;

    const int B = in_sizes[2];  // rel has B elements

    net_gather_kernel<<<B / WARPS, 32 * WARPS>>>(data_r, data_e, rel,
                                                 pos_id, neg_id,
                                                 ent_emb, edge_w, rel_emb,
                                                 out, B);
}

// round 6
// speedup vs baseline: 1.0137x; 1.0137x over previous
#include <cuda_runtime.h>
#include <cuda_bf16.h>

#define DIM   128
#define NNB   64
#define WARPS 2        // rows per block (fine-grained load balance)

// One warp per batch row. Lane l owns dims [4l, 4l+3] (float4).
// Gathers use __ldcg (L2-only: rows reuse in L2, never in L1).
// Outputs use __stcs (streaming: don't pollute L2 holding the gather set).
__global__ void __launch_bounds__(32 * WARPS, 16)
net_gather_kernel(const int* __restrict__ data_r,
                  const int* __restrict__ data_e,
                  const int* __restrict__ rel,
                  const int* __restrict__ pos_id,
                  const int* __restrict__ neg_id,
                  const float* __restrict__ ent_emb,
                  const float* __restrict__ edge_w,
                  const float* __restrict__ rel_emb,
                  float* __restrict__ out,
                  int B)
{
    const int w    = threadIdx.x >> 5;
    const int lane = threadIdx.x & 31;
    const int b    = blockIdx.x * WARPS + w;

    __shared__ int   s_e[WARPS][NNB];   // entity row index * 32 (float4 stride)
    __shared__ float s_w[WARPS][NNB];   // softmax weights

    // Stage indices (prescaled to float4 row offset) and edge logits.
    const int base = b * NNB;
    s_e[w][lane]      = data_e[base + lane]      * (DIM / 4);
    s_e[w][lane + 32] = data_e[base + lane + 32] * (DIM / 4);
    float l0 = __ldg(&edge_w[data_r[base + lane]]);
    float l1 = __ldg(&edge_w[data_r[base + lane + 32]]);

    // Warp-local softmax over 64 logits (2 per lane).
    float m = fmaxf(l0, l1);
    #pragma unroll
    for (int off = 16; off > 0; off >>= 1)
        m = fmaxf(m, __shfl_xor_sync(0xffffffffu, m, off));
    float x0 = __expf(l0 - m);
    float x1 = __expf(l1 - m);
    float s = x0 + x1;
    #pragma unroll
    for (int off = 16; off > 0; off >>= 1)
        s += __shfl_xor_sync(0xffffffffu, s, off);
    float inv = __frcp_rn(s);
    s_w[w][lane]      = x0 * inv;
    s_w[w][lane + 32] = x1 * inv;
    __syncwarp();

    const float4* __restrict__ emb4 = (const float4*)ent_emb;   // row stride 32

    // Independent per-row lookups issued early (overlap with gather loop).
    float4 rv = __ldg(&((const float4*)rel_emb)[rel[b] * (DIM / 4) + lane]);
    float4 pv = __ldcg(&emb4[pos_id[b] * (DIM / 4) + lane]);
    float4 nv = __ldcg(&emb4[neg_id[b] * (DIM / 4) + lane]);

    // Weighted gather-sum: 8 LDG.128 in flight per chunk, 2 float4 accumulators.
    float4 A = make_float4(0.f, 0.f, 0.f, 0.f);
    float4 C = make_float4(0.f, 0.f, 0.f, 0.f);
    #pragma unroll
    for (int j = 0; j < NNB; j += 8) {
        float4 v[8];
        float  wt[8];
        #pragma unroll
        for (int k = 0; k < 8; k++) {
            v[k]  = __ldcg(&emb4[s_e[w][j + k] + lane]);
            wt[k] = s_w[w][j + k];
        }
        #pragma unroll
        for (int k = 0; k < 8; k += 2) {
            A.x = fmaf(wt[k], v[k].x, A.x);
            A.y = fmaf(wt[k], v[k].y, A.y);
            A.z = fmaf(wt[k], v[k].z, A.z);
            A.w = fmaf(wt[k], v[k].w, A.w);
            C.x = fmaf(wt[k + 1], v[k + 1].x, C.x);
            C.y = fmaf(wt[k + 1], v[k + 1].y, C.y);
            C.z = fmaf(wt[k + 1], v[k + 1].z, C.z);
            C.w = fmaf(wt[k + 1], v[k + 1].w, C.w);
        }
    }

    float4 o;
    o.x = A.x + C.x + rv.x;
    o.y = A.y + C.y + rv.y;
    o.z = A.z + C.z + rv.z;
    o.w = A.w + C.w + rv.w;

    float4* out4 = (float4*)out;
    const int bd = b * (DIM / 4) + lane;
    const int BD = B * (DIM / 4);
    __stcs(&out4[bd],          o);
    __stcs(&out4[BD + bd],     pv);
    __stcs(&out4[2 * BD + bd], nv);
}

extern "C" void kernel_launch(void* const* d_in, const int* in_sizes, int n_in,
                              void* d_out, int out_size)
{
    const int*   data_r  = (const int*)  d_in[0];
    const int*   data_e  = (const int*)  d_in[1];
    const int*   rel     = (const int*)  d_in[2];
    const int*   pos_id  = (const int*)  d_in[3];
    const int*   neg_id  = (const int*)  d_in[4];
    const float* ent_emb = (const float*)d_in[5];
    const float* edge_w  = (const float*)d_in[6];
    const float* rel_emb = (const float*)d_in[7];
    float* out = (float*)d_out;

    const int B = in_sizes[2];  // rel has B elements

    net_gather_kernel<<<B / WARPS, 32 * WARPS>>>(data_r, data_e, rel,
                                                 pos_id, neg_id,
                                                 ent_emb, edge_w, rel_emb,
                                                 out, B);
}